// round 1
// baseline (speedup 1.0000x reference)
#include <cuda_runtime.h>
#include <cuda_bf16.h>

// Word2Vec SGNS loss:
//   loss = sum_b -logsig(dot(U[pos_u[b]], V[pos_v[b]]))
//        + sum_{b,k} -logsig(dot(U[neg_u[b,k]], V[neg_v[b,k]]))
// One warp per edge: 32 lanes x float2 = 64 floats (256B, two 128B lines) per
// gathered row -> perfectly coalesced gathers from both tables.

#define THREADS 256
#define WARPS_PER_BLOCK (THREADS / 32)

__global__ void zero_out_kernel(float* out) {
    out[0] = 0.0f;
}

__global__ __launch_bounds__(THREADS) void sgns_loss_kernel(
    const int* __restrict__ pos_u,
    const int* __restrict__ pos_v,
    const int* __restrict__ neg_u,
    const int* __restrict__ neg_v,
    const float* __restrict__ u_emb,
    const float* __restrict__ v_emb,
    float* __restrict__ out,
    int B,
    int total)   // B * (K + 1)
{
    const int warp_in_block = threadIdx.x >> 5;
    const int lane = threadIdx.x & 31;
    const int warp = blockIdx.x * WARPS_PER_BLOCK + warp_in_block;

    float loss = 0.0f;

    if (warp < total) {
        int ui, vi;
        if (warp < B) {
            ui = __ldg(pos_u + warp);
            vi = __ldg(pos_v + warp);
        } else {
            int t = warp - B;   // flattened [B, K] index
            ui = __ldg(neg_u + t);
            vi = __ldg(neg_v + t);
        }

        const float2* __restrict__ up =
            reinterpret_cast<const float2*>(u_emb + (size_t)ui * 64);
        const float2* __restrict__ vp =
            reinterpret_cast<const float2*>(v_emb + (size_t)vi * 64);

        float2 a = __ldg(up + lane);
        float2 b = __ldg(vp + lane);
        float dot = a.x * b.x + a.y * b.y;

        // warp tree-reduce the 64-element dot product
        #pragma unroll
        for (int off = 16; off > 0; off >>= 1)
            dot += __shfl_xor_sync(0xFFFFFFFFu, dot, off);

        if (lane == 0) {
            // -logsigmoid(x) = max(-x, 0) + log1p(exp(-|x|))  (stable)
            float x = dot;
            loss = fmaxf(-x, 0.0f) + log1pf(expf(-fabsf(x)));
        }
    }

    // block reduce: one partial per warp -> one atomicAdd per block
    __shared__ float smem[WARPS_PER_BLOCK];
    if (lane == 0) smem[warp_in_block] = loss;
    __syncthreads();

    if (warp_in_block == 0) {
        float v = (lane < WARPS_PER_BLOCK) ? smem[lane] : 0.0f;
        #pragma unroll
        for (int off = WARPS_PER_BLOCK / 2; off > 0; off >>= 1)
            v += __shfl_xor_sync(0xFFFFFFFFu, v, off);
        if (lane == 0) atomicAdd(out, v);
    }
}

extern "C" void kernel_launch(void* const* d_in, const int* in_sizes, int n_in,
                              void* d_out, int out_size) {
    const int* pos_u = (const int*)d_in[0];
    const int* pos_v = (const int*)d_in[1];
    const int* neg_u = (const int*)d_in[2];
    const int* neg_v = (const int*)d_in[3];
    const float* u_emb = (const float*)d_in[4];
    const float* v_emb = (const float*)d_in[5];
    float* out = (float*)d_out;

    const int B = in_sizes[0];          // 16384
    const int BK = in_sizes[2];         // B * K
    const int total = B + BK;           // B * (K + 1)

    zero_out_kernel<<<1, 1>>>(out);

    const int blocks = (total + WARPS_PER_BLOCK - 1) / WARPS_PER_BLOCK;
    sgns_loss_kernel<<<blocks, THREADS>>>(pos_u, pos_v, neg_u, neg_v,
                                          u_emb, v_emb, out, B, total);
}

// round 2
// speedup vs baseline: 2.8276x; 2.8276x over previous
#include <cuda_runtime.h>
#include <cuda_bf16.h>

// Word2Vec SGNS loss, latency-optimized:
//   - 16 lanes x float4 = one 256B row per half-warp; each load instruction
//     gathers TWO rows (edge A in lanes 0-15, edge B in lanes 16-31).
//   - 8 edges per warp, fully unrolled -> 8 independent float4 gathers in
//     flight (MLP=8) before any consumer.
//   - butterfly reduce within 16-lane halves (4 shfls reduce 2 edges at once).

#define THREADS 256
#define WARPS_PER_BLOCK (THREADS / 32)
#define PAIRS 4                      // 2 edges per pair -> 8 edges per warp
#define EDGES_PER_WARP (2 * PAIRS)

__global__ void zero_out_kernel(float* out) {
    out[0] = 0.0f;
}

__global__ __launch_bounds__(THREADS) void sgns_loss_kernel(
    const int* __restrict__ pos_u,
    const int* __restrict__ pos_v,
    const int* __restrict__ neg_u,
    const int* __restrict__ neg_v,
    const float* __restrict__ u_emb,
    const float* __restrict__ v_emb,
    float* __restrict__ out,
    int B,
    int total)   // B * (K + 1)
{
    const int warp_in_block = threadIdx.x >> 5;
    const int lane = threadIdx.x & 31;
    const int half = lane >> 4;          // which edge of the pair this lane serves
    const int l16 = lane & 15;           // lane within the 16-lane row group
    const long long warp = (long long)blockIdx.x * WARPS_PER_BLOCK + warp_in_block;
    const long long base = warp * EDGES_PER_WARP;

    int ui[PAIRS], vi[PAIRS];
    bool valid[PAIRS];

    // Phase 1: index gathers (broadcast loads, cheap)
    #pragma unroll
    for (int p = 0; p < PAIRS; p++) {
        long long e = base + 2 * p + half;
        valid[p] = (e < total);
        long long es = valid[p] ? e : 0;
        if (es < B) {
            ui[p] = __ldg(pos_u + es);
            vi[p] = __ldg(pos_v + es);
        } else {
            long long t = es - B;
            ui[p] = __ldg(neg_u + t);
            vi[p] = __ldg(neg_v + t);
        }
    }

    // Phase 2: 8 independent 256B row gathers (MLP = 8)
    float4 a[PAIRS], b[PAIRS];
    #pragma unroll
    for (int p = 0; p < PAIRS; p++) {
        a[p] = __ldg(reinterpret_cast<const float4*>(
                   u_emb + (size_t)ui[p] * 64) + l16);
        b[p] = __ldg(reinterpret_cast<const float4*>(
                   v_emb + (size_t)vi[p] * 64) + l16);
    }

    // Phase 3: per-lane partial dots + 16-lane butterfly (reduces both
    // halves' edges simultaneously; after this every lane of a half holds
    // the full dot for its edge)
    float loss = 0.0f;
    #pragma unroll
    for (int p = 0; p < PAIRS; p++) {
        float dot = a[p].x * b[p].x + a[p].y * b[p].y
                  + a[p].z * b[p].z + a[p].w * b[p].w;
        #pragma unroll
        for (int off = 8; off > 0; off >>= 1)
            dot += __shfl_xor_sync(0xFFFFFFFFu, dot, off);

        // -logsigmoid(x) = max(-x,0) + log1p(exp(-|x|)); computed
        // redundantly on all 16 lanes (SIMD, no extra wall time)
        float l = fmaxf(-dot, 0.0f) + log1pf(expf(-fabsf(dot)));
        loss += valid[p] ? l : 0.0f;
    }

    // Combine the two halves: all lanes of each half hold identical loss
    loss += __shfl_xor_sync(0xFFFFFFFFu, loss, 16);
    // Now every lane holds this warp's total.

    __shared__ float smem[WARPS_PER_BLOCK];
    if (lane == 0) smem[warp_in_block] = loss;
    __syncthreads();

    if (warp_in_block == 0) {
        float v = (lane < WARPS_PER_BLOCK) ? smem[lane] : 0.0f;
        #pragma unroll
        for (int off = WARPS_PER_BLOCK / 2; off > 0; off >>= 1)
            v += __shfl_xor_sync(0xFFFFFFFFu, v, off);
        if (lane == 0) atomicAdd(out, v);
    }
}

extern "C" void kernel_launch(void* const* d_in, const int* in_sizes, int n_in,
                              void* d_out, int out_size) {
    const int* pos_u = (const int*)d_in[0];
    const int* pos_v = (const int*)d_in[1];
    const int* neg_u = (const int*)d_in[2];
    const int* neg_v = (const int*)d_in[3];
    const float* u_emb = (const float*)d_in[4];
    const float* v_emb = (const float*)d_in[5];
    float* out = (float*)d_out;

    const int B = in_sizes[0];          // 16384
    const int BK = in_sizes[2];         // B * K
    const int total = B + BK;           // B * (K + 1)

    zero_out_kernel<<<1, 1>>>(out);

    const int edges_per_block = WARPS_PER_BLOCK * EDGES_PER_WARP;
    const int blocks = (total + edges_per_block - 1) / edges_per_block;
    sgns_loss_kernel<<<blocks, THREADS>>>(pos_u, pos_v, neg_u, neg_v,
                                          u_emb, v_emb, out, B, total);
}